// round 11
// baseline (speedup 1.0000x reference)
#include <cuda_runtime.h>
#include <cstdint>

// ExtractPatch: B=8, H=W=1024, N=4096 matches, R=8 -> 17x17 patches.
// out[bn][k]        = normalize(img1[b, my1 + k%17 - 8, mx1 + k/17 - 8])   k in [0,289)
// out[bn][289 + k]  = normalize(img2[b, my2 + k%17 - 8, mx2 + k/17 - 8])
// normalize: (p - mean) / (std_ddof1 + 1e-4), zero-padded outside image.
//
// Write path experiment: normalized output staged in smem, stored to gmem via
// cp.async.bulk (async bulk engine) instead of per-thread STG.

#define D      17
#define PATCH  289
#define HW     1024
#define NMATCH 4096
#define BATCH  8
#define WPB    4
#define THREADS (WPB * 32)
#define PPW    2                   // pairs of matches per warp
#define PAIRW  1156                // floats per pair (2 matches x 578)
#define PAIRB  4624                // bytes per pair (16-aligned)

__device__ __forceinline__ uint64_t pack2(float lo, float hi) {
    uint64_t r;
    asm("mov.b64 %0, {%1, %2};" : "=l"(r) : "f"(lo), "f"(hi));
    return r;
}
__device__ __forceinline__ void unpack2(uint64_t v, float& lo, float& hi) {
    asm("mov.b64 {%0, %1}, %2;" : "=f"(lo), "=f"(hi) : "l"(v));
}
__device__ __forceinline__ uint64_t add2(uint64_t a, uint64_t b) {
    uint64_t r;
    asm("add.rn.f32x2 %0, %1, %2;" : "=l"(r) : "l"(a), "l"(b));
    return r;
}
__device__ __forceinline__ uint64_t fma2(uint64_t a, uint64_t b, uint64_t c) {
    uint64_t r;
    asm("fma.rn.f32x2 %0, %1, %2, %3;" : "=l"(r) : "l"(a), "l"(b), "l"(c));
    return r;
}
__device__ __forceinline__ uint64_t shfl_xor2(uint64_t v, int mask) {
    uint32_t lo = (uint32_t)v, hi = (uint32_t)(v >> 32);
    lo = __shfl_xor_sync(0xffffffffu, lo, mask);
    hi = __shfl_xor_sync(0xffffffffu, hi, mask);
    return (uint64_t)lo | ((uint64_t)hi << 32);
}
__device__ __forceinline__ uint32_t smem_u32(const void* p) {
    return (uint32_t)__cvta_generic_to_shared(p);
}

__global__ __launch_bounds__(THREADS, 6)
void extract_patch_kernel(const float* __restrict__ img1,
                          const float* __restrict__ img2,
                          const int*   __restrict__ matches,
                          float*       __restrict__ out)
{
    // Per-warp staging: PPW buffers of one pair each (transposed = final layout).
    __shared__ __align__(16) float Stage[WPB][PPW][PAIRW];

    const int warpId = threadIdx.x >> 5;
    const int lane   = threadIdx.x & 31;

    const int wg    = blockIdx.x * WPB + warpId;     // 0 .. 8191
    const int pair0 = wg * PPW;

    // initial (r, c) for this lane: idx = lane, r = idx/17, c = idx%17
    const int c0 = (lane >= D) ? (lane - D) : lane;
    const int r0 = (lane >= D) ? 1 : 0;

    #pragma unroll
    for (int pp = 0; pp < PPW; ++pp) {
        const int pair = pair0 + pp;
        float* __restrict__ SB = Stage[warpId][pp];

        #pragma unroll
        for (int mmi = 0; mmi < 2; ++mmi) {
            const int bn = 2 * pair + mmi;            // match id
            const int b  = bn >> 12;                  // batch

            const float* __restrict__ ib1 = img1 + (size_t)b * (HW * HW);
            const float* __restrict__ ib2 = img2 + (size_t)b * (HW * HW);
            const int4 m = __ldg((const int4*)(matches + (size_t)bn * 4));

            float* __restrict__ Tw = SB + mmi * (2 * PATCH);

            uint64_t S = 0, Q = 0;   // packed (s1,s2), (q1,q2)

            const bool interior =
                ((unsigned)(m.x - 8) <= (HW - D)) & ((unsigned)(m.y - 8) <= (HW - D)) &
                ((unsigned)(m.z - 8) <= (HW - D)) & ((unsigned)(m.w - 8) <= (HW - D));

            if (interior) {
                const float* p1 = ib1 + (m.y - 8) * HW + (m.x - 8);
                const float* p2 = ib2 + (m.w - 8) * HW + (m.z - 8);
                int c   = c0;
                int d   = r0 * HW + c0;
                int sts = c0 * D + r0;               // transposed index = c*17 + r
                #pragma unroll
                for (int t = 0; t < 10; ++t) {
                    if (t < 9 || lane == 0) {
                        const float v1 = __ldg(p1 + d);
                        const float v2 = __ldg(p2 + d);
                        Tw[sts]         = v1;
                        Tw[PATCH + sts] = v2;
                        const uint64_t v = pack2(v1, v2);
                        S = add2(S, v);
                        Q = fma2(v, v, Q);
                    }
                    c   += 15;
                    d   += HW + 15;
                    sts += 15 * D + 1;
                    if (c >= D) {
                        c   -= D;
                        d   += HW - D;
                        sts -= D * D - 1;            // -288
                    }
                }
            } else {
                const int x1 = m.x - 8, y1 = m.y - 8;
                const int x2 = m.z - 8, y2 = m.w - 8;
                int c = c0, r = r0;
                int sts = c0 * D + r0;
                #pragma unroll
                for (int t = 0; t < 10; ++t) {
                    if (t < 9 || lane == 0) {
                        const int yy1 = y1 + r, xx1 = x1 + c;
                        const int yy2 = y2 + r, xx2 = x2 + c;
                        float v1 = 0.f, v2 = 0.f;
                        if (((unsigned)yy1 < HW) & ((unsigned)xx1 < HW))
                            v1 = __ldg(ib1 + yy1 * HW + xx1);
                        if (((unsigned)yy2 < HW) & ((unsigned)xx2 < HW))
                            v2 = __ldg(ib2 + yy2 * HW + xx2);
                        Tw[sts]         = v1;
                        Tw[PATCH + sts] = v2;
                        const uint64_t v = pack2(v1, v2);
                        S = add2(S, v);
                        Q = fma2(v, v, Q);
                    }
                    c += 15; r += 1; sts += 15 * D + 1;
                    if (c >= D) { c -= D; r += 1; sts -= D * D - 1; }
                }
            }

            // ---- packed warp reduction ----
            #pragma unroll
            for (int o = 16; o > 0; o >>= 1) {
                S = add2(S, shfl_xor2(S, o));
                Q = add2(Q, shfl_xor2(Q, o));
            }
            float s1, s2, q1, q2;
            unpack2(S, s1, s2);
            unpack2(Q, q1, q2);

            const float mean1 = s1 * (1.0f / PATCH);
            const float mean2 = s2 * (1.0f / PATCH);
            float var1 = fmaxf((q1 - (float)PATCH * mean1 * mean1) * (1.0f / (PATCH - 1)), 0.f);
            float var2 = fmaxf((q2 - (float)PATCH * mean2 * mean2) * (1.0f / (PATCH - 1)), 0.f);
            const float inv1 = 1.0f / (sqrtf(var1) + 1e-4f);
            const float inv2 = 1.0f / (sqrtf(var2) + 1e-4f);
            const float bb1  = -mean1 * inv1;   // (v - m)*i = v*i + (-m*i)
            const float bb2  = -mean2 * inv2;

            const uint64_t A1 = pack2(inv1, inv1), B1 = pack2(bb1, bb1);
            const uint64_t A2 = pack2(inv2, inv2), B2 = pack2(bb2, bb2);

            __syncwarp();   // scatter visible to all lanes

            // ---- in-place normalize: 289 float2 (8B-aligned) ----
            uint64_t* __restrict__ Ts = (uint64_t*)Tw;
            #pragma unroll
            for (int t = 0; t < 10; ++t) {
                const int k = t * 32 + lane;      // float2 index, valid k < 289
                if (t < 9 || lane == 0) {
                    const uint64_t v = Ts[k];
                    uint64_t A, B;
                    if (t < 4)      { A = A1; B = B1; }
                    else if (t > 4) { A = A2; B = B2; }
                    else {
                        // boundary: elem 2k patch1 iff k<=144; 2k+1 patch1 iff k<=143
                        const float aLo = (k <= 144) ? inv1 : inv2, bLo = (k <= 144) ? bb1 : bb2;
                        const float aHi = (k <= 143) ? inv1 : inv2, bHi = (k <= 143) ? bb1 : bb2;
                        A = pack2(aLo, aHi); B = pack2(bLo, bHi);
                    }
                    Ts[k] = fma2(v, A, B);
                }
            }
        }

        __syncwarp();   // both matches staged & normalized

        // ---- bulk store: one async 4624B smem->gmem copy per pair ----
        if (lane == 0) {
            asm volatile("fence.proxy.async.shared::cta;" ::: "memory");
            asm volatile(
                "cp.async.bulk.global.shared::cta.bulk_group [%0], [%1], %2;"
                :: "l"(out + (size_t)pair * PAIRW), "r"(smem_u32(SB)), "r"(PAIRB)
                : "memory");
            asm volatile("cp.async.bulk.commit_group;" ::: "memory");
        }
        // PPW=2 with independent buffers: no intra-kernel reuse wait needed.
    }

    // drain outstanding bulk stores before exit
    if (lane == 0)
        asm volatile("cp.async.bulk.wait_group 0;" ::: "memory");
}

extern "C" void kernel_launch(void* const* d_in, const int* in_sizes, int n_in,
                              void* d_out, int out_size)
{
    const float* img1    = (const float*)d_in[0];
    const float* img2    = (const float*)d_in[1];
    const int*   matches = (const int*)d_in[2];
    float*       out     = (float*)d_out;

    const int total_pairs = BATCH * NMATCH / 2;               // 16384
    const int blocks = total_pairs / (WPB * PPW);             // 2048

    extract_patch_kernel<<<blocks, THREADS>>>(img1, img2, matches, out);
}

// round 12
// speedup vs baseline: 1.4122x; 1.4122x over previous
#include <cuda_runtime.h>
#include <cstdint>

// ExtractPatch: B=8, H=W=1024, N=4096 matches, R=8 -> 17x17 patches.
// out[bn][k]        = normalize(img1[b, my1 + k%17 - 8, mx1 + k/17 - 8])   k in [0,289)
// out[bn][289 + k]  = normalize(img2[b, my2 + k%17 - 8, mx2 + k/17 - 8])
// normalize: (p - mean) / (std_ddof1 + 1e-4), zero-padded outside image.
//
// Warp handles a PAIR of consecutive matches: gather+reduce each (R5-proven
// path), stage raw values transposed in smem, then write both with 10
// STG.128 (1156 floats = 289 aligned float4) using per-element coeff select.

#define D      17
#define PATCH  289
#define HW     1024
#define NMATCH 4096
#define BATCH  8
#define WPB    4
#define THREADS (WPB * 32)
#define PAIRW  1156            // floats per pair

__device__ __forceinline__ uint64_t pack2(float lo, float hi) {
    uint64_t r;
    asm("mov.b64 %0, {%1, %2};" : "=l"(r) : "f"(lo), "f"(hi));
    return r;
}
__device__ __forceinline__ void unpack2(uint64_t v, float& lo, float& hi) {
    asm("mov.b64 {%0, %1}, %2;" : "=f"(lo), "=f"(hi) : "l"(v));
}
__device__ __forceinline__ uint64_t add2(uint64_t a, uint64_t b) {
    uint64_t r;
    asm("add.rn.f32x2 %0, %1, %2;" : "=l"(r) : "l"(a), "l"(b));
    return r;
}
__device__ __forceinline__ uint64_t fma2(uint64_t a, uint64_t b, uint64_t c) {
    uint64_t r;
    asm("fma.rn.f32x2 %0, %1, %2, %3;" : "=l"(r) : "l"(a), "l"(b), "l"(c));
    return r;
}
__device__ __forceinline__ uint64_t shfl_xor2(uint64_t v, int mask) {
    uint32_t lo = (uint32_t)v, hi = (uint32_t)(v >> 32);
    lo = __shfl_xor_sync(0xffffffffu, lo, mask);
    hi = __shfl_xor_sync(0xffffffffu, hi, mask);
    return (uint64_t)lo | ((uint64_t)hi << 32);
}

__global__ __launch_bounds__(THREADS, 8)
void extract_patch_kernel(const float* __restrict__ img1,
                          const float* __restrict__ img2,
                          const int*   __restrict__ matches,
                          float*       __restrict__ out)
{
    // Per-warp staging for one PAIR (transposed = final layout), 16B aligned.
    __shared__ __align__(16) float Tr[WPB][PAIRW];

    const int warpId = threadIdx.x >> 5;
    const int lane   = threadIdx.x & 31;

    const int pair = blockIdx.x * WPB + warpId;   // 0 .. 16383
    const int bn0  = pair * 2;
    const int b    = bn0 >> 12;                   // same batch for both (4096 even)

    const float* __restrict__ ib1 = img1 + (size_t)b * (HW * HW);
    const float* __restrict__ ib2 = img2 + (size_t)b * (HW * HW);

    float* __restrict__ Trw = Tr[warpId];

    // initial (r, c) for this lane: idx = lane, r = idx/17, c = idx%17
    const int c0 = (lane >= D) ? (lane - D) : lane;
    const int r0 = (lane >= D) ? 1 : 0;

    // per-patch normalize coefficients: a[p], bb[p] for p = 0..3
    float av[4], bv[4];

    #pragma unroll
    for (int mi = 0; mi < 2; ++mi) {
        const int bn = bn0 + mi;
        const int4 m = __ldg((const int4*)(matches + (size_t)bn * 4));
        float* __restrict__ Tw = Trw + mi * (2 * PATCH);

        uint64_t S = 0, Q = 0;

        const bool interior =
            ((unsigned)(m.x - 8) <= (HW - D)) & ((unsigned)(m.y - 8) <= (HW - D)) &
            ((unsigned)(m.z - 8) <= (HW - D)) & ((unsigned)(m.w - 8) <= (HW - D));

        if (interior) {
            const float* p1 = ib1 + (m.y - 8) * HW + (m.x - 8);
            const float* p2 = ib2 + (m.w - 8) * HW + (m.z - 8);
            int c   = c0;
            int d   = r0 * HW + c0;
            int sts = c0 * D + r0;               // transposed index = c*17 + r
            #pragma unroll
            for (int t = 0; t < 10; ++t) {
                if (t < 9 || lane == 0) {
                    const float v1 = __ldg(p1 + d);
                    const float v2 = __ldg(p2 + d);
                    Tw[sts]         = v1;
                    Tw[PATCH + sts] = v2;
                    const uint64_t v = pack2(v1, v2);
                    S = add2(S, v);
                    Q = fma2(v, v, Q);
                }
                c   += 15;
                d   += HW + 15;
                sts += 15 * D + 1;
                if (c >= D) {
                    c   -= D;
                    d   += HW - D;
                    sts -= D * D - 1;            // -288
                }
            }
        } else {
            const int x1 = m.x - 8, y1 = m.y - 8;
            const int x2 = m.z - 8, y2 = m.w - 8;
            int c = c0, r = r0;
            int sts = c0 * D + r0;
            #pragma unroll
            for (int t = 0; t < 10; ++t) {
                if (t < 9 || lane == 0) {
                    const int yy1 = y1 + r, xx1 = x1 + c;
                    const int yy2 = y2 + r, xx2 = x2 + c;
                    float v1 = 0.f, v2 = 0.f;
                    if (((unsigned)yy1 < HW) & ((unsigned)xx1 < HW))
                        v1 = __ldg(ib1 + yy1 * HW + xx1);
                    if (((unsigned)yy2 < HW) & ((unsigned)xx2 < HW))
                        v2 = __ldg(ib2 + yy2 * HW + xx2);
                    Tw[sts]         = v1;
                    Tw[PATCH + sts] = v2;
                    const uint64_t v = pack2(v1, v2);
                    S = add2(S, v);
                    Q = fma2(v, v, Q);
                }
                c += 15; r += 1; sts += 15 * D + 1;
                if (c >= D) { c -= D; r += 1; sts -= D * D - 1; }
            }
        }

        // packed warp reduction
        #pragma unroll
        for (int o = 16; o > 0; o >>= 1) {
            S = add2(S, shfl_xor2(S, o));
            Q = add2(Q, shfl_xor2(Q, o));
        }
        float s1, s2, q1, q2;
        unpack2(S, s1, s2);
        unpack2(Q, q1, q2);

        const float mean1 = s1 * (1.0f / PATCH);
        const float mean2 = s2 * (1.0f / PATCH);
        float var1 = fmaxf((q1 - (float)PATCH * mean1 * mean1) * (1.0f / (PATCH - 1)), 0.f);
        float var2 = fmaxf((q2 - (float)PATCH * mean2 * mean2) * (1.0f / (PATCH - 1)), 0.f);
        const float i1 = 1.0f / (sqrtf(var1) + 1e-4f);
        const float i2 = 1.0f / (sqrtf(var2) + 1e-4f);
        av[2 * mi]     = i1;  bv[2 * mi]     = -mean1 * i1;
        av[2 * mi + 1] = i2;  bv[2 * mi + 1] = -mean2 * i2;
    }

    __syncwarp();

    // ---- paired write: 289 float4 over 1156 contiguous floats (16B aligned) ----
    float4* __restrict__ ob = (float4*)(out + (size_t)pair * PAIRW);
    const float4* __restrict__ Ts = (const float4*)Trw;

    #pragma unroll
    for (int t = 0; t < 10; ++t) {
        const int k = t * 32 + lane;          // float4 index, valid k < 289
        if (t < 9 || lane == 0) {
            const float4 v = Ts[k];
            const int e0 = 4 * k;             // element index of v.x
            // patch id per element: e/289 (0..3); piecewise-uniform per tile
            float a0, b0, a1, b1, a2, b2, a3, b3;
            if ((e0 >> 2) * 4 + 3 < PATCH || t < 2) {              // fully patch 0 region
                a0 = a1 = a2 = a3 = av[0]; b0 = b1 = b2 = b3 = bv[0];
            } else {
                const int p0 = e0 / PATCH,       p1 = (e0 + 1) / PATCH;
                const int p2 = (e0 + 2) / PATCH, p3 = (e0 + 3) / PATCH;
                a0 = av[p0]; b0 = bv[p0];
                a1 = av[p1]; b1 = bv[p1];
                a2 = av[p2]; b2 = bv[p2];
                a3 = av[p3]; b3 = bv[p3];
            }
            float4 w;
            w.x = fmaf(v.x, a0, b0);
            w.y = fmaf(v.y, a1, b1);
            w.z = fmaf(v.z, a2, b2);
            w.w = fmaf(v.w, a3, b3);
            __stcs(&ob[k], w);
        }
    }
}

extern "C" void kernel_launch(void* const* d_in, const int* in_sizes, int n_in,
                              void* d_out, int out_size)
{
    const float* img1    = (const float*)d_in[0];
    const float* img2    = (const float*)d_in[1];
    const int*   matches = (const int*)d_in[2];
    float*       out     = (float*)d_out;

    const int total_pairs = BATCH * NMATCH / 2;     // 16384
    const int blocks = total_pairs / WPB;           // 4096

    extract_patch_kernel<<<blocks, THREADS>>>(img1, img2, matches, out);
}